// round 1
// baseline (speedup 1.0000x reference)
#include <cuda_runtime.h>
#include <math.h>

#define B 32
#define L 64
#define E 512
#define H 1024
#define G4 4096
#define V 32000

// ---------------- scratch state (device globals; no allocs) ----------------
__device__ float d_h[B*H];
__device__ float d_c[B*H];
__device__ float d_encouts[B*L*H];      // [b][l][j]
__device__ float d_gpart[8][B][G4];     // K-split partials for gate GEMMs
__device__ float d_cpart[8][B][H];      // K-split partials for combine GEMM
__device__ float d_e[B*H];              // decoder embedding of current token
__device__ float d_ctx[B*H];            // attention context
__device__ int   d_tok[B];              // greedy token feedback

__device__ __forceinline__ float sigmoidf_(float x){ return 1.f/(1.f+expf(-x)); }

// ---------------- init ----------------
__global__ void k_init_enc(){
  int idx = blockIdx.x*256 + threadIdx.x;
  if (idx < B*H){ d_h[idx]=0.f; d_c[idx]=0.f; }
}
__global__ void k_init_dec(){
  int idx = blockIdx.x*256 + threadIdx.x;
  if (idx < B*H){ d_h[idx]=0.f; d_c[idx]=0.f; }
  if (idx < B) d_tok[idx] = 127;
}

// ---------------- encoder gates GEMM (K-split, embed gather fused) ----------------
// gates_partial[ks] = concat(embed_row, h) @ [enc_wx; enc_wh]   (K chunk per ks)
// grid 128 = 16 jblk (64 hidden each) x 8 ksplit (192 K each); 256 threads.
__global__ void k_enc_gemm(const int* __restrict__ x, const float* __restrict__ emb,
                           const float* __restrict__ wx, const float* __restrict__ wh, int t){
  __shared__ float sa[32][64];
  int tid = threadIdx.x;
  int ks = blockIdx.x & 7;
  int jblk = blockIdx.x >> 3;
  int j0 = jblk*64;
  int jl = tid & 63, bg = tid >> 6;     // bg: 4 groups x 8 batches
  float acc[8][4];
  #pragma unroll
  for (int i=0;i<8;i++){
    #pragma unroll
    for (int g=0;g<4;g++) acc[i][g]=0.f;
  }
  for (int kc=0; kc<3; kc++){
    int kbase = ks*192 + kc*64;
    #pragma unroll
    for (int r=0;r<8;r++){
      int idx = tid + r*256; int b = idx>>6, kk = idx&63; int k = kbase+kk;
      float v;
      if (k < E) v = emb[(size_t)x[b*L+t]*E + k];
      else       v = d_h[b*H + (k-E)];
      sa[b][kk] = v;
    }
    __syncthreads();
    const float* Wb = (kbase < E) ? (wx + (size_t)kbase*G4) : (wh + (size_t)(kbase-E)*G4);
    #pragma unroll 4
    for (int kk=0; kk<64; kk++){
      const float* W = Wb + (size_t)kk*G4 + j0 + jl;
      float w0=W[0], w1=W[1024], w2=W[2048], w3=W[3072];
      #pragma unroll
      for (int i=0;i<8;i++){
        float a = sa[bg*8+i][kk];
        acc[i][0] += a*w0; acc[i][1] += a*w1; acc[i][2] += a*w2; acc[i][3] += a*w3;
      }
    }
    __syncthreads();
  }
  #pragma unroll
  for (int i=0;i<8;i++){
    int b = bg*8+i;
    #pragma unroll
    for (int g=0;g<4;g++) d_gpart[ks][b][g*1024 + j0 + jl] = acc[i][g];
  }
}

// ---------------- encoder pointwise LSTM update ----------------
__global__ void k_enc_point(const float* __restrict__ bias, int t){
  int idx = blockIdx.x*256 + threadIdx.x;   // < 32768
  int b = idx >> 10, j = idx & 1023;
  float gi = bias[j], gf = bias[j+1024], gg = bias[j+2048], go = bias[j+3072];
  #pragma unroll
  for (int p=0;p<8;p++){
    gi += d_gpart[p][b][j];
    gf += d_gpart[p][b][j+1024];
    gg += d_gpart[p][b][j+2048];
    go += d_gpart[p][b][j+3072];
  }
  float c = d_c[idx];
  c = sigmoidf_(gf)*c + sigmoidf_(gi)*tanhf(gg);
  float h = sigmoidf_(go)*tanhf(c);
  d_c[idx]=c; d_h[idx]=h;
  d_encouts[(b*L + t)*H + j] = h;
}

// ---------------- decoder: embed + attention + softmax + context (fused) ----------------
// grid 32 (one block per batch row), 256 threads
__global__ void k_dec_attn(const float* __restrict__ demb, const float* __restrict__ aw_w,
                           const float* __restrict__ aw_b){
  __shared__ float spart[256];
  __shared__ float s_logit[64];
  __shared__ float s_aw[64];
  __shared__ float s_red[2];
  int b = blockIdx.x, tid = threadIdx.x;
  int tok = d_tok[b];
  const float* erow = demb + (size_t)tok*H;
  // materialize e for the combine GEMM
  #pragma unroll
  for (int r=0;r<4;r++){ int j = tid + r*256; d_e[b*H+j] = erow[j]; }
  // attention logits: col = tid%64, 4-way K split reduced in shared
  int col = tid & 63, kg = tid >> 6;
  float acc = 0.f;
  int k0 = kg*512;
  for (int k=k0; k<k0+512; k++){
    float a = (k < H) ? erow[k] : d_h[b*H + (k-H)];
    acc += a * aw_w[k*64 + col];
  }
  spart[tid] = acc;
  __syncthreads();
  if (tid < 64)
    s_logit[tid] = spart[tid] + spart[tid+64] + spart[tid+128] + spart[tid+192] + aw_b[tid];
  __syncthreads();
  if (tid < 32){
    float m = fmaxf(s_logit[tid], s_logit[tid+32]);
    #pragma unroll
    for (int o=16;o>0;o>>=1) m = fmaxf(m, __shfl_xor_sync(0xffffffffu, m, o));
    if (tid==0) s_red[0]=m;
  }
  __syncthreads();
  if (tid < 64) s_aw[tid] = expf(s_logit[tid] - s_red[0]);
  __syncthreads();
  if (tid < 32){
    float s = s_aw[tid] + s_aw[tid+32];
    #pragma unroll
    for (int o=16;o>0;o>>=1) s += __shfl_xor_sync(0xffffffffu, s, o);
    if (tid==0) s_red[1]=s;
  }
  __syncthreads();
  float inv = 1.f / s_red[1];
  // context: thread owns 4 consecutive j (vectorized)
  int j4 = tid*4;
  float4 cacc = make_float4(0.f,0.f,0.f,0.f);
  for (int l=0;l<64;l++){
    float w = s_aw[l]*inv;
    const float4 v = *(const float4*)&d_encouts[(b*L + l)*H + j4];
    cacc.x += w*v.x; cacc.y += w*v.y; cacc.z += w*v.z; cacc.w += w*v.w;
  }
  *(float4*)&d_ctx[b*H + j4] = cacc;
}

// ---------------- decoder combine GEMM partials: concat(e, ctx) @ comb_w ----------------
// grid 128 = 16 jblk x 8 ksplit (256 K each); 256 threads
__global__ void k_dec_comb(const float* __restrict__ w){
  __shared__ float sa[32][64];
  int tid = threadIdx.x;
  int ks = blockIdx.x & 7, jblk = blockIdx.x >> 3;
  int j0 = jblk*64;
  int jl = tid & 63, bg = tid >> 6;
  float acc[8];
  #pragma unroll
  for (int i=0;i<8;i++) acc[i]=0.f;
  for (int kc=0;kc<4;kc++){
    int kbase = ks*256 + kc*64;
    #pragma unroll
    for (int r=0;r<8;r++){
      int idx = tid + r*256; int b = idx>>6, kk = idx&63; int k = kbase+kk;
      sa[b][kk] = (k < H) ? d_e[b*H+k] : d_ctx[b*H + (k-H)];
    }
    __syncthreads();
    #pragma unroll 4
    for (int kk=0;kk<64;kk++){
      float wv = w[(size_t)(kbase+kk)*H + j0 + jl];
      #pragma unroll
      for (int i=0;i<8;i++) acc[i] += sa[bg*8+i][kk]*wv;
    }
    __syncthreads();
  }
  #pragma unroll
  for (int i=0;i<8;i++) d_cpart[ks][bg*8+i][j0+jl] = acc[i];
}

// ---------------- decoder gates GEMM (combine-reduce + bias + relu fused into loader) ----
// grid 128 = 16 jblk x 8 ksplit (256 K each); 256 threads
__global__ void k_dec_gates(const float* __restrict__ wx, const float* __restrict__ wh,
                            const float* __restrict__ comb_b){
  __shared__ float sa[32][64];
  int tid = threadIdx.x;
  int ks = blockIdx.x & 7, jblk = blockIdx.x >> 3;
  int j0 = jblk*64;
  int jl = tid & 63, bg = tid >> 6;
  float acc[8][4];
  #pragma unroll
  for (int i=0;i<8;i++){
    #pragma unroll
    for (int g=0;g<4;g++) acc[i][g]=0.f;
  }
  for (int kc=0;kc<4;kc++){
    int kbase = ks*256 + kc*64;
    #pragma unroll
    for (int r=0;r<8;r++){
      int idx = tid + r*256; int b = idx>>6, kk = idx&63; int k = kbase+kk;
      float v;
      if (k < H){
        float s = comb_b[k];
        #pragma unroll
        for (int p=0;p<8;p++) s += d_cpart[p][b][k];
        v = fmaxf(s, 0.f);                 // relu(combine) fused here
      } else {
        v = d_h[b*H + (k-H)];
      }
      sa[b][kk]=v;
    }
    __syncthreads();
    const float* Wb = (kbase < H) ? (wx + (size_t)kbase*G4) : (wh + (size_t)(kbase-H)*G4);
    #pragma unroll 4
    for (int kk=0;kk<64;kk++){
      const float* W = Wb + (size_t)kk*G4 + j0 + jl;
      float w0=W[0],w1=W[1024],w2=W[2048],w3=W[3072];
      #pragma unroll
      for (int i=0;i<8;i++){
        float a = sa[bg*8+i][kk];
        acc[i][0]+=a*w0; acc[i][1]+=a*w1; acc[i][2]+=a*w2; acc[i][3]+=a*w3;
      }
    }
    __syncthreads();
  }
  #pragma unroll
  for (int i=0;i<8;i++){
    int b = bg*8+i;
    #pragma unroll
    for (int g=0;g<4;g++) d_gpart[ks][b][g*1024 + j0 + jl] = acc[i][g];
  }
}

// ---------------- decoder pointwise LSTM update ----------------
__global__ void k_dec_point(const float* __restrict__ bias){
  int idx = blockIdx.x*256 + threadIdx.x;
  int b = idx >> 10, j = idx & 1023;
  float gi = bias[j], gf = bias[j+1024], gg = bias[j+2048], go = bias[j+3072];
  #pragma unroll
  for (int p=0;p<8;p++){
    gi += d_gpart[p][b][j];
    gf += d_gpart[p][b][j+1024];
    gg += d_gpart[p][b][j+2048];
    go += d_gpart[p][b][j+3072];
  }
  float c = d_c[idx];
  c = sigmoidf_(gf)*c + sigmoidf_(gi)*tanhf(gg);
  float h = sigmoidf_(go)*tanhf(c);
  d_c[idx]=c; d_h[idx]=h;
}

// ---------------- output projection: raw logits straight into d_out ----------------
// grid 500 (64 vocab cols each); 256 threads = 64 cols x 4 batch-groups
__global__ void k_logits(const float* __restrict__ ow, const float* __restrict__ ob,
                         float* __restrict__ out, int t){
  __shared__ float sh[32][128];
  int tid = threadIdx.x;
  int col0 = blockIdx.x*64;
  int cl = tid & 63, bg = tid >> 6;
  float acc[8];
  #pragma unroll
  for (int i=0;i<8;i++) acc[i]=0.f;
  for (int kc=0;kc<8;kc++){
    int kbase = kc*128;
    #pragma unroll
    for (int r=0;r<16;r++){
      int idx = tid + r*256; int b = idx>>7, kk = idx&127;
      sh[b][kk] = d_h[b*H + kbase + kk];
    }
    __syncthreads();
    #pragma unroll 4
    for (int kk=0;kk<128;kk++){
      float wv = ow[(size_t)(kbase+kk)*V + col0 + cl];
      #pragma unroll
      for (int i=0;i<8;i++) acc[i] += sh[bg*8+i][kk]*wv;
    }
    __syncthreads();
  }
  float bv = ob[col0+cl];
  #pragma unroll
  for (int i=0;i<8;i++){
    int b = bg*8+i;
    out[(size_t)(b*L + t)*V + col0 + cl] = acc[i] + bv;
  }
}

// ---------------- log_softmax in place + argmax -> next token ----------------
__global__ void k_lsm_argmax(float* __restrict__ out, int t){
  __shared__ float smax[256]; __shared__ int sidx[256]; __shared__ float ssum[256];
  __shared__ float s_M, s_S;
  int b = blockIdx.x, tid = threadIdx.x;
  float* row = out + (size_t)(b*L + t)*V;
  float m = -INFINITY; int mi = 0;
  for (int v = tid; v < V; v += 256){
    float val = row[v];
    if (val > m){ m = val; mi = v; }      // strict > keeps first occurrence
  }
  smax[tid]=m; sidx[tid]=mi;
  __syncthreads();
  for (int s=128; s>0; s>>=1){
    if (tid < s){
      float om = smax[tid+s]; int oi = sidx[tid+s];
      if (om > smax[tid] || (om == smax[tid] && oi < sidx[tid])){ smax[tid]=om; sidx[tid]=oi; }
    }
    __syncthreads();
  }
  if (tid==0){ s_M = smax[0]; d_tok[b] = sidx[0]; }
  __syncthreads();
  float M = s_M;
  float ssm = 0.f;
  for (int v = tid; v < V; v += 256) ssm += expf(row[v]-M);
  ssum[tid]=ssm; __syncthreads();
  for (int s=128;s>0;s>>=1){ if (tid<s) ssum[tid]+=ssum[tid+s]; __syncthreads(); }
  if (tid==0) s_S = ssum[0];
  __syncthreads();
  float lse = M + logf(s_S);
  for (int v = tid; v < V; v += 256) row[v] = row[v] - lse;
}

// ---------------- launcher (graph-capturable: kernel launches only) ----------------
extern "C" void kernel_launch(void* const* d_in, const int* in_sizes, int n_in,
                              void* d_out, int out_size){
  const int*   x         = (const int*)  d_in[0];
  const float* enc_embed = (const float*)d_in[1];
  const float* enc_wx    = (const float*)d_in[2];
  const float* enc_wh    = (const float*)d_in[3];
  const float* enc_b     = (const float*)d_in[4];
  const float* dec_embed = (const float*)d_in[5];
  const float* attn_w    = (const float*)d_in[6];
  const float* attn_b    = (const float*)d_in[7];
  const float* comb_w    = (const float*)d_in[8];
  const float* comb_b    = (const float*)d_in[9];
  const float* dec_wx    = (const float*)d_in[10];
  const float* dec_wh    = (const float*)d_in[11];
  const float* dec_b     = (const float*)d_in[12];
  const float* out_w     = (const float*)d_in[13];
  const float* out_b     = (const float*)d_in[14];
  float* out = (float*)d_out;

  k_init_enc<<<128,256>>>();
  for (int t=0;t<64;t++){
    k_enc_gemm<<<128,256>>>(x, enc_embed, enc_wx, enc_wh, t);
    k_enc_point<<<128,256>>>(enc_b, t);
  }
  k_init_dec<<<128,256>>>();
  for (int t=0;t<64;t++){
    k_dec_attn<<<32,256>>>(dec_embed, attn_w, attn_b);
    k_dec_comb<<<128,256>>>(comb_w);
    k_dec_gates<<<128,256>>>(dec_wx, dec_wh, comb_b);
    k_dec_point<<<128,256>>>(dec_b);
    k_logits<<<500,256>>>(out_w, out_b, out, t);
    k_lsm_argmax<<<32,256>>>(out, t);
  }
}

// round 2
// speedup vs baseline: 1.9473x; 1.9473x over previous
#include <cuda_runtime.h>
#include <math.h>

#define B 32
#define L 64
#define E 512
#define H 1024
#define G4 4096
#define V 32000
#define VH 16000   // V/2 (u32 bf16-pairs per weight row)

typedef unsigned int u32;
typedef unsigned long long u64;

// ---------------- scratch state (device globals; no allocs) ----------------
__device__ float d_h[B*H];
__device__ float d_c[B*H];
__device__ float d_encouts[B*L*H];       // [b][l][j]
__device__ float d_xg[L][B][G4];         // precomputed emb@enc_wx + enc_b  (32MB)
__device__ float d_gpart[16][B][G4];     // K-split partials for gate GEMMs (8MB)
__device__ float d_cpart[16][B][H];      // K-split partials for combine GEMM
__device__ float d_cin[B*H];             // relu(combine)
__device__ float d_e[B*H];               // decoder embedding of current token
__device__ float d_ctx[B*H];             // attention context
__device__ int   d_tok[B];
__device__ u32   d_oww[H*VH];            // out_w as bf16 pairs, [K][V/2] (64MB)
__device__ float d_lpart[2][B][V];       // logits K-split partials (8MB)
__device__ float d_lm[B][8];             // per-chunk max
__device__ float d_ls[B][8];             // per-chunk expsum
__device__ int   d_li[B][8];             // per-chunk argmax

__device__ __forceinline__ float sigmoidf_(float x){ return 1.f/(1.f+expf(-x)); }
__device__ __forceinline__ u64 bcast_f(float x){ u64 r; asm("mov.b64 %0,{%1,%1};" : "=l"(r) : "f"(x)); return r; }
__device__ __forceinline__ u64 bcast_b(u32 fb){ u64 r; asm("mov.b64 %0,{%1,%1};" : "=l"(r) : "r"(fb)); return r; }
__device__ __forceinline__ void fma2(u64& d, u64 a, u64 b){ asm("fma.rn.f32x2 %0,%1,%2,%0;" : "+l"(d) : "l"(a), "l"(b)); }
__device__ __forceinline__ float lo_(u64 v){ return __uint_as_float((u32)v); }
__device__ __forceinline__ float hi_(u64 v){ return __uint_as_float((u32)(v>>32)); }
__device__ __forceinline__ u32 f2bf(float f){ u32 b=__float_as_uint(f); return (b + 0x7fffu + ((b>>16)&1u))>>16; }

// ---------------- init ----------------
__global__ void k_init(){
  int idx = blockIdx.x*256 + threadIdx.x;
  if (idx < B*H){ d_h[idx]=0.f; d_c[idx]=0.f; }
  if (idx < B) d_tok[idx] = 127;
}

// ---------------- one-time: out_w fp32 -> bf16 pairs ----------------
__global__ void k_conv_ow(const float* __restrict__ ow){
  const float2* src = (const float2*)ow;
  size_t base = (size_t)blockIdx.x*2048;
  #pragma unroll
  for (int r=0;r<8;r++){
    size_t i = base + r*256 + threadIdx.x;   // 8000*2048 = 16,384,000 exactly
    float2 v = src[i];
    d_oww[i] = (f2bf(v.y)<<16) | f2bf(v.x);
  }
}

// ---------------- one-time: xg[t] = emb(x_t) @ enc_wx + enc_b ----------------
// grid 2048 = 64 t x 32 colblk(128 cols); 256 threads
__global__ void k_xg(const int* __restrict__ x, const float* __restrict__ emb,
                     const float* __restrict__ wx, const float* __restrict__ eb){
  __shared__ float2 sh2[16][64];
  int tid = threadIdx.x;
  int t = blockIdx.x >> 5;
  int colbase = (blockIdx.x & 31)*128;
  int cl = tid & 63, bg = tid >> 6;
  u64 acc[2][4] = {};
  for (int kc=0;kc<8;kc++){
    int kb = kc*64;
    #pragma unroll
    for (int r=0;r<4;r++){
      int idx=tid+r*256; int bp=idx>>6, kk=idx&63; int k = kb+kk;
      sh2[bp][kk] = make_float2(emb[(size_t)x[(2*bp)*L+t]*E + k],
                                emb[(size_t)x[(2*bp+1)*L+t]*E + k]);
    }
    __syncthreads();
    #pragma unroll 8
    for (int kk=0;kk<64;kk++){
      float2 w = *(const float2*)(wx + (size_t)(kb+kk)*G4 + colbase + 2*cl);
      u64 wa = bcast_f(w.x), wb = bcast_f(w.y);
      #pragma unroll
      for (int bp=0;bp<4;bp++){
        u64 a = *(const u64*)&sh2[bg*4+bp][kk];
        fma2(acc[0][bp],a,wa); fma2(acc[1][bp],a,wb);
      }
    }
    __syncthreads();
  }
  int c0 = colbase + 2*cl;
  float e0 = eb[c0], e1 = eb[c0+1];
  #pragma unroll
  for (int bp=0;bp<4;bp++){
    int b0 = bg*8 + 2*bp;
    *(float2*)&d_xg[t][b0][c0]   = make_float2(lo_(acc[0][bp])+e0, lo_(acc[1][bp])+e1);
    *(float2*)&d_xg[t][b0+1][c0] = make_float2(hi_(acc[0][bp])+e0, hi_(acc[1][bp])+e1);
  }
}

// ---------------- encoder recurrent GEMM: h @ enc_wh -> gpart ----------------
// grid 512 = 32 colblk(128) x 16 ksplit(K=64); 256 threads
__global__ void k_enc_gemm(const float* __restrict__ wh){
  __shared__ float2 sh2[16][64];
  int tid = threadIdx.x;
  int ks = blockIdx.x & 15;
  int colbase = (blockIdx.x >> 4)*128;
  int kb = ks*64;
  int cl = tid & 63, bg = tid >> 6;
  u64 acc[2][4] = {};
  #pragma unroll
  for (int r=0;r<4;r++){
    int idx=tid+r*256; int bp=idx>>6, kk=idx&63;
    sh2[bp][kk] = make_float2(d_h[(2*bp)*H + kb+kk], d_h[(2*bp+1)*H + kb+kk]);
  }
  __syncthreads();
  #pragma unroll 8
  for (int kk=0;kk<64;kk++){
    float2 w = *(const float2*)(wh + (size_t)(kb+kk)*G4 + colbase + 2*cl);
    u64 wa = bcast_f(w.x), wb = bcast_f(w.y);
    #pragma unroll
    for (int bp=0;bp<4;bp++){
      u64 a = *(const u64*)&sh2[bg*4+bp][kk];
      fma2(acc[0][bp],a,wa); fma2(acc[1][bp],a,wb);
    }
  }
  int c0 = colbase + 2*cl;
  #pragma unroll
  for (int bp=0;bp<4;bp++){
    int b0 = bg*8 + 2*bp;
    *(float2*)&d_gpart[ks][b0][c0]   = make_float2(lo_(acc[0][bp]), lo_(acc[1][bp]));
    *(float2*)&d_gpart[ks][b0+1][c0] = make_float2(hi_(acc[0][bp]), hi_(acc[1][bp]));
  }
}

// ---------------- encoder pointwise ----------------
__global__ void k_enc_point(int t){
  int idx = blockIdx.x*256 + threadIdx.x;   // 32768
  int b = idx >> 10, j = idx & 1023;
  float g0 = d_xg[t][b][j],      g1 = d_xg[t][b][j+1024];
  float g2 = d_xg[t][b][j+2048], g3 = d_xg[t][b][j+3072];
  #pragma unroll
  for (int p=0;p<16;p++){
    g0 += d_gpart[p][b][j];      g1 += d_gpart[p][b][j+1024];
    g2 += d_gpart[p][b][j+2048]; g3 += d_gpart[p][b][j+3072];
  }
  float c = d_c[idx];
  c = sigmoidf_(g1)*c + sigmoidf_(g0)*tanhf(g2);
  float h = sigmoidf_(g3)*tanhf(c);
  d_c[idx]=c; d_h[idx]=h;
  d_encouts[(b*L + t)*H + j] = h;
}

// ---------------- decoder: embed + attention + softmax + context ----------------
__global__ void k_dec_attn(const float* __restrict__ demb, const float* __restrict__ aw_w,
                           const float* __restrict__ aw_b){
  __shared__ float spart[256];
  __shared__ float s_logit[64];
  __shared__ float s_aw[64];
  __shared__ float s_red[2];
  int b = blockIdx.x, tid = threadIdx.x;
  int tok = d_tok[b];
  const float* erow = demb + (size_t)tok*H;
  #pragma unroll
  for (int r=0;r<4;r++){ int j = tid + r*256; d_e[b*H+j] = erow[j]; }
  int col = tid & 63, kg = tid >> 6;
  float acc = 0.f;
  int k0 = kg*512;
  for (int k=k0; k<k0+512; k++){
    float a = (k < H) ? erow[k] : d_h[b*H + (k-H)];
    acc += a * aw_w[k*64 + col];
  }
  spart[tid] = acc;
  __syncthreads();
  if (tid < 64)
    s_logit[tid] = spart[tid] + spart[tid+64] + spart[tid+128] + spart[tid+192] + aw_b[tid];
  __syncthreads();
  if (tid < 32){
    float m = fmaxf(s_logit[tid], s_logit[tid+32]);
    #pragma unroll
    for (int o=16;o>0;o>>=1) m = fmaxf(m, __shfl_xor_sync(0xffffffffu, m, o));
    if (tid==0) s_red[0]=m;
  }
  __syncthreads();
  if (tid < 64) s_aw[tid] = expf(s_logit[tid] - s_red[0]);
  __syncthreads();
  if (tid < 32){
    float s = s_aw[tid] + s_aw[tid+32];
    #pragma unroll
    for (int o=16;o>0;o>>=1) s += __shfl_xor_sync(0xffffffffu, s, o);
    if (tid==0) s_red[1]=s;
  }
  __syncthreads();
  float inv = 1.f / s_red[1];
  int j4 = tid*4;
  float4 cacc = make_float4(0.f,0.f,0.f,0.f);
  for (int l=0;l<64;l++){
    float w = s_aw[l]*inv;
    const float4 v = *(const float4*)&d_encouts[(b*L + l)*H + j4];
    cacc.x += w*v.x; cacc.y += w*v.y; cacc.z += w*v.z; cacc.w += w*v.w;
  }
  *(float4*)&d_ctx[b*H + j4] = cacc;
}

// ---------------- combine GEMM: concat(e,ctx) @ comb_w -> cpart ----------------
// grid 128 = 8 colblk(128) x 16 ksplit(K=128); 256 threads
__global__ void k_dec_comb(const float* __restrict__ w){
  __shared__ float2 sh2[16][64];
  int tid = threadIdx.x;
  int ks = blockIdx.x & 15;
  int colbase = (blockIdx.x >> 4)*128;
  int cl = tid & 63, bg = tid >> 6;
  u64 acc[2][4] = {};
  for (int kc=0;kc<2;kc++){
    int kb = ks*128 + kc*64;
    #pragma unroll
    for (int r=0;r<4;r++){
      int idx=tid+r*256; int bp=idx>>6, kk=idx&63; int k = kb+kk;
      float a0,a1;
      if (k < H){ a0 = d_e[(2*bp)*H + k];       a1 = d_e[(2*bp+1)*H + k]; }
      else      { a0 = d_ctx[(2*bp)*H + (k-H)]; a1 = d_ctx[(2*bp+1)*H + (k-H)]; }
      sh2[bp][kk] = make_float2(a0, a1);
    }
    __syncthreads();
    #pragma unroll 8
    for (int kk=0;kk<64;kk++){
      float2 wv = *(const float2*)(w + (size_t)(kb+kk)*H + colbase + 2*cl);
      u64 wa = bcast_f(wv.x), wb = bcast_f(wv.y);
      #pragma unroll
      for (int bp=0;bp<4;bp++){
        u64 a = *(const u64*)&sh2[bg*4+bp][kk];
        fma2(acc[0][bp],a,wa); fma2(acc[1][bp],a,wb);
      }
    }
    __syncthreads();
  }
  int c0 = colbase + 2*cl;
  #pragma unroll
  for (int bp=0;bp<4;bp++){
    int b0 = bg*8 + 2*bp;
    *(float2*)&d_cpart[ks][b0][c0]   = make_float2(lo_(acc[0][bp]), lo_(acc[1][bp]));
    *(float2*)&d_cpart[ks][b0+1][c0] = make_float2(hi_(acc[0][bp]), hi_(acc[1][bp]));
  }
}

// ---------------- combine finalize: reduce + bias + relu ----------------
__global__ void k_combfin(const float* __restrict__ cb){
  int idx = blockIdx.x*256 + threadIdx.x;   // 32768
  int b = idx >> 10, j = idx & 1023;
  float s = cb[j];
  #pragma unroll
  for (int p=0;p<16;p++) s += d_cpart[p][b][j];
  d_cin[idx] = fmaxf(s, 0.f);
}

// ---------------- decoder gates GEMM: concat(cin,h) @ [wx;wh] -> gpart ----------------
// grid 512 = 32 colblk(128) x 16 ksplit(K=128); 256 threads
__global__ void k_dec_gates(const float* __restrict__ wx, const float* __restrict__ wh){
  __shared__ float2 sh2[16][64];
  int tid = threadIdx.x;
  int ks = blockIdx.x & 15;
  int colbase = (blockIdx.x >> 4)*128;
  int cl = tid & 63, bg = tid >> 6;
  u64 acc[2][4] = {};
  for (int kc=0;kc<2;kc++){
    int kb = ks*128 + kc*64;
    #pragma unroll
    for (int r=0;r<4;r++){
      int idx=tid+r*256; int bp=idx>>6, kk=idx&63; int k = kb+kk;
      float a0,a1;
      if (k < H){ a0 = d_cin[(2*bp)*H + k];     a1 = d_cin[(2*bp+1)*H + k]; }
      else      { a0 = d_h[(2*bp)*H + (k-H)];   a1 = d_h[(2*bp+1)*H + (k-H)]; }
      sh2[bp][kk] = make_float2(a0, a1);
    }
    __syncthreads();
    const float* Wb = (kb < H) ? (wx + (size_t)kb*G4) : (wh + (size_t)(kb-H)*G4);
    #pragma unroll 8
    for (int kk=0;kk<64;kk++){
      float2 wv = *(const float2*)(Wb + (size_t)kk*G4 + colbase + 2*cl);
      u64 wa = bcast_f(wv.x), wb2 = bcast_f(wv.y);
      #pragma unroll
      for (int bp=0;bp<4;bp++){
        u64 a = *(const u64*)&sh2[bg*4+bp][kk];
        fma2(acc[0][bp],a,wa); fma2(acc[1][bp],a,wb2);
      }
    }
    __syncthreads();
  }
  int c0 = colbase + 2*cl;
  #pragma unroll
  for (int bp=0;bp<4;bp++){
    int b0 = bg*8 + 2*bp;
    *(float2*)&d_gpart[ks][b0][c0]   = make_float2(lo_(acc[0][bp]), lo_(acc[1][bp]));
    *(float2*)&d_gpart[ks][b0+1][c0] = make_float2(hi_(acc[0][bp]), hi_(acc[1][bp]));
  }
}

// ---------------- decoder pointwise ----------------
__global__ void k_dec_point(const float* __restrict__ db){
  int idx = blockIdx.x*256 + threadIdx.x;
  int b = idx >> 10, j = idx & 1023;
  float g0 = db[j], g1 = db[j+1024], g2 = db[j+2048], g3 = db[j+3072];
  #pragma unroll
  for (int p=0;p<16;p++){
    g0 += d_gpart[p][b][j];      g1 += d_gpart[p][b][j+1024];
    g2 += d_gpart[p][b][j+2048]; g3 += d_gpart[p][b][j+3072];
  }
  float c = d_c[idx];
  c = sigmoidf_(g1)*c + sigmoidf_(g0)*tanhf(g2);
  float h = sigmoidf_(g3)*tanhf(c);
  d_c[idx]=c; d_h[idx]=h;
}

// ---------------- logits: h @ out_w(bf16) -> lpart ----------------
// grid 250 = 125 colblk(256 cols) x 2 ksplit(K=512); 256 threads
// thread: 4 cols x 8 batches (4 batch-pair f32x2 accumulators per col)
__global__ void k_logits(){
  __shared__ float2 sh2[16][64];
  int tid = threadIdx.x;
  int ks = blockIdx.x & 1;
  int colbase = (blockIdx.x >> 1)*256;
  int cl = tid & 63, bg = tid >> 6;
  u64 acc[4][4] = {};
  int kbase = ks*512;
  for (int kc=0;kc<8;kc++){
    int kb = kbase + kc*64;
    #pragma unroll
    for (int r=0;r<4;r++){
      int idx=tid+r*256; int bp=idx>>6, kk=idx&63;
      sh2[bp][kk] = make_float2(d_h[(2*bp)*H + kb+kk], d_h[(2*bp+1)*H + kb+kk]);
    }
    __syncthreads();
    const u32* wrow = d_oww + (size_t)kb*VH + (colbase>>1);
    #pragma unroll 4
    for (int kk=0;kk<64;kk++){
      u64 wu = *(const u64*)(wrow + (size_t)kk*VH + 2*cl);
      u32 wl = (u32)wu, wh2 = (u32)(wu>>32);
      u64 w0 = bcast_b(wl<<16);
      u64 w1 = bcast_b(wl & 0xffff0000u);
      u64 w2 = bcast_b(wh2<<16);
      u64 w3 = bcast_b(wh2 & 0xffff0000u);
      #pragma unroll
      for (int bp=0;bp<4;bp++){
        u64 a = *(const u64*)&sh2[bg*4+bp][kk];
        fma2(acc[0][bp],a,w0); fma2(acc[1][bp],a,w1);
        fma2(acc[2][bp],a,w2); fma2(acc[3][bp],a,w3);
      }
    }
    __syncthreads();
  }
  int c0 = colbase + 4*cl;
  #pragma unroll
  for (int bp=0;bp<4;bp++){
    int b0 = bg*8 + 2*bp;
    *(float4*)&d_lpart[ks][b0][c0]   = make_float4(lo_(acc[0][bp]),lo_(acc[1][bp]),lo_(acc[2][bp]),lo_(acc[3][bp]));
    *(float4*)&d_lpart[ks][b0+1][c0] = make_float4(hi_(acc[0][bp]),hi_(acc[1][bp]),hi_(acc[2][bp]),hi_(acc[3][bp]));
  }
}

// ---------------- log-softmax stage 1: merge partials + bias, chunk stats ----------------
// grid 256 = 32 rows x 8 vchunks(4000)
__global__ void k_lsm1(const float* __restrict__ ob, float* __restrict__ out, int t){
  __shared__ float sm[256]; __shared__ int si[256]; __shared__ float ss[256];
  int b = blockIdx.x & 31, ch = blockIdx.x >> 5;
  int tid = threadIdx.x;
  int v0 = ch*4000;
  float* row = out + (size_t)(b*L + t)*V;
  float m = -INFINITY; int mi = 0;
  for (int v = v0+tid; v < v0+4000; v += 256){
    float val = d_lpart[0][b][v] + d_lpart[1][b][v] + ob[v];
    row[v] = val;
    if (val > m){ m = val; mi = v; }
  }
  sm[tid]=m; si[tid]=mi;
  __syncthreads();
  for (int s=128;s>0;s>>=1){
    if (tid < s){
      float om=sm[tid+s]; int oi=si[tid+s];
      if (om > sm[tid] || (om == sm[tid] && oi < si[tid])){ sm[tid]=om; si[tid]=oi; }
    }
    __syncthreads();
  }
  float M = sm[0];
  float se = 0.f;
  for (int v = v0+tid; v < v0+4000; v += 256) se += expf(row[v] - M);
  ss[tid]=se; __syncthreads();
  for (int s=128;s>0;s>>=1){ if (tid<s) ss[tid]+=ss[tid+s]; __syncthreads(); }
  if (tid==0){ d_lm[b][ch]=M; d_ls[b][ch]=ss[0]; d_li[b][ch]=si[0]; }
}

// ---------------- log-softmax stage 2: combine stats, subtract lse, emit token ----------
// grid 512 = 32 rows x 16 vchunks(2000)
__global__ void k_lsm2(float* __restrict__ out, int t){
  int b = blockIdx.x & 31, ch = blockIdx.x >> 5;
  int tid = threadIdx.x;
  float M = -INFINITY; int mi = 0;
  #pragma unroll
  for (int c=0;c<8;c++){
    float lm = d_lm[b][c]; int li = d_li[b][c];
    if (lm > M || (lm == M && li < mi)){ M = lm; mi = li; }
  }
  float S = 0.f;
  #pragma unroll
  for (int c=0;c<8;c++) S += d_ls[b][c]*expf(d_lm[b][c] - M);
  float lse = M + logf(S);
  if (ch==0 && tid==0) d_tok[b] = mi;
  float* row = out + (size_t)(b*L + t)*V;
  int v0 = ch*2000;
  for (int v = v0+tid; v < v0+2000; v += 256) row[v] -= lse;
}

// ---------------- launcher ----------------
extern "C" void kernel_launch(void* const* d_in, const int* in_sizes, int n_in,
                              void* d_out, int out_size){
  const int*   x         = (const int*)  d_in[0];
  const float* enc_embed = (const float*)d_in[1];
  const float* enc_wx    = (const float*)d_in[2];
  const float* enc_wh    = (const float*)d_in[3];
  const float* enc_b     = (const float*)d_in[4];
  const float* dec_embed = (const float*)d_in[5];
  const float* attn_w    = (const float*)d_in[6];
  const float* attn_b    = (const float*)d_in[7];
  const float* comb_w    = (const float*)d_in[8];
  const float* comb_b    = (const float*)d_in[9];
  const float* dec_wx    = (const float*)d_in[10];
  const float* dec_wh    = (const float*)d_in[11];
  const float* dec_b     = (const float*)d_in[12];
  const float* out_w     = (const float*)d_in[13];
  const float* out_b     = (const float*)d_in[14];
  float* out = (float*)d_out;

  k_init<<<128,256>>>();
  k_conv_ow<<<8000,256>>>(out_w);
  k_xg<<<2048,256>>>(x, enc_embed, enc_wx, enc_b);
  for (int t=0;t<64;t++){
    k_enc_gemm<<<512,256>>>(enc_wh);
    k_enc_point<<<128,256>>>(t);
  }
  k_init<<<128,256>>>();
  for (int t=0;t<64;t++){
    k_dec_attn<<<32,256>>>(dec_embed, attn_w, attn_b);
    k_dec_comb<<<128,256>>>(comb_w);
    k_combfin<<<128,256>>>(comb_b);
    k_dec_gates<<<512,256>>>(dec_wx, dec_wh);
    k_dec_point<<<128,256>>>(dec_b);
    k_logits<<<250,256>>>();
    k_lsm1<<<256,256>>>(out_b, out, t);
    k_lsm2<<<512,256>>>(out, t);
  }
}

// round 7
// speedup vs baseline: 3.2012x; 1.6439x over previous
#include <cuda_runtime.h>
#include <math.h>
#include <stdint.h>

#define B 32
#define L 64
#define E 512
#define H 1024
#define G4 4096
#define V 32000

typedef unsigned int u32;
typedef unsigned long long u64;

// ---------------- scratch state (device globals; no allocs) ----------------
__device__ float d_h[B*H];
__device__ float d_c[B*H];
__device__ float d_encouts[B*L*H];       // [b][l][j]
__device__ float d_xg[L][B][G4];         // precomputed emb@enc_wx + enc_b
__device__ float d_gpart[16][B][G4];     // K-split partials for gate GEMMs
__device__ float d_cpart[16][B][H];      // K-split partials for combine GEMM
__device__ float d_cin[B*H];             // relu(combine)
__device__ float d_e[B*H];               // decoder embedding of current token
__device__ float d_ctx[B*H];             // attention context
__device__ float d_apart[8][B][64];      // attention logit partials
__device__ int   d_tok[B];
__device__ u32   d_owT[(size_t)V*512];   // out_w transposed: [V][K/2] bf16-pairs (64MB)
__device__ float d_lm2[B*250];           // per-(b,colchunk) max
__device__ float d_ls2[B*250];           // per-(b,colchunk) expsum
__device__ int   d_li2[B*250];           // per-(b,colchunk) argmax

__device__ __forceinline__ float sigmoidf_(float x){ return 1.f/(1.f+expf(-x)); }
__device__ __forceinline__ u64 bcast_f(float x){ u64 r; asm("mov.b64 %0,{%1,%1};" : "=l"(r) : "f"(x)); return r; }
__device__ __forceinline__ void fma2(u64& d, u64 a, u64 b){ asm("fma.rn.f32x2 %0,%1,%2,%0;" : "+l"(d) : "l"(a), "l"(b)); }
__device__ __forceinline__ float lo_(u64 v){ return __uint_as_float((u32)v); }
__device__ __forceinline__ float hi_(u64 v){ return __uint_as_float((u32)(v>>32)); }
__device__ __forceinline__ u32 f2bf(float f){ u32 b=__float_as_uint(f); return (b + 0x7fffu + ((b>>16)&1u))>>16; }

// classic tensor-core mma (sm_80+, no arch-suffix PTX -> compiles for sm_103)
__device__ __forceinline__ void mma_bf16(float* d, u32 a0,u32 a1,u32 a2,u32 a3,u32 b0,u32 b1){
  asm volatile("mma.sync.aligned.m16n8k16.row.col.f32.bf16.bf16.f32 "
    "{%0,%1,%2,%3}, {%4,%5,%6,%7}, {%8,%9}, {%0,%1,%2,%3};"
    : "+f"(d[0]),"+f"(d[1]),"+f"(d[2]),"+f"(d[3])
    : "r"(a0),"r"(a1),"r"(a2),"r"(a3),"r"(b0),"r"(b1));
}

// ---------------- init ----------------
__global__ void k_init(){
  int idx = blockIdx.x*256 + threadIdx.x;
  if (idx < B*H){ d_h[idx]=0.f; d_c[idx]=0.f; }
  if (idx < B) d_tok[idx] = 127;
}

// ---------------- one-time: out_w [K][V] fp32 -> d_owT [V][K] bf16 pairs ----------------
// grid 8000 = 500 vblk(64) x 16 kblk(64); 256 threads
__global__ void k_conv_owT(const float* __restrict__ ow){
  __shared__ float sh[64][65];
  int vblk = blockIdx.x % 500, kblk = blockIdx.x / 500;
  int v0 = vblk*64, k0 = kblk*64;
  int tid = threadIdx.x;
  int vc = tid & 63, kg = tid >> 6;
  #pragma unroll
  for (int r=0;r<16;r++){
    int kr = kg*16 + r;
    sh[kr][vc] = ow[(size_t)(k0+kr)*V + v0 + vc];
  }
  __syncthreads();
  int vl = tid >> 2, p0 = (tid & 3)*8;
  u32* dst = d_owT + (size_t)(v0+vl)*512 + (k0>>1);
  #pragma unroll
  for (int q=0;q<8;q++){
    int p = p0 + q;
    dst[p] = (f2bf(sh[2*p+1][vl])<<16) | f2bf(sh[2*p][vl]);
  }
}

// ---------------- one-time: xg[t] = emb(x_t) @ enc_wx + enc_b ----------------
__global__ void k_xg(const int* __restrict__ x, const float* __restrict__ emb,
                     const float* __restrict__ wx, const float* __restrict__ eb){
  __shared__ float2 sh2[16][64];
  int tid = threadIdx.x;
  int t = blockIdx.x >> 5;
  int colbase = (blockIdx.x & 31)*128;
  int cl = tid & 63, bg = tid >> 6;
  u64 acc[2][4] = {};
  for (int kc=0;kc<8;kc++){
    int kb = kc*64;
    #pragma unroll
    for (int r=0;r<4;r++){
      int idx=tid+r*256; int bp=idx>>6, kk=idx&63; int k = kb+kk;
      sh2[bp][kk] = make_float2(emb[(size_t)x[(2*bp)*L+t]*E + k],
                                emb[(size_t)x[(2*bp+1)*L+t]*E + k]);
    }
    __syncthreads();
    #pragma unroll 8
    for (int kk=0;kk<64;kk++){
      float2 w = *(const float2*)(wx + (size_t)(kb+kk)*G4 + colbase + 2*cl);
      u64 wa = bcast_f(w.x), wb = bcast_f(w.y);
      #pragma unroll
      for (int bp=0;bp<4;bp++){
        u64 a = *(const u64*)&sh2[bg*4+bp][kk];
        fma2(acc[0][bp],a,wa); fma2(acc[1][bp],a,wb);
      }
    }
    __syncthreads();
  }
  int c0 = colbase + 2*cl;
  float e0 = eb[c0], e1 = eb[c0+1];
  #pragma unroll
  for (int bp=0;bp<4;bp++){
    int b0 = bg*8 + 2*bp;
    *(float2*)&d_xg[t][b0][c0]   = make_float2(lo_(acc[0][bp])+e0, lo_(acc[1][bp])+e1);
    *(float2*)&d_xg[t][b0+1][c0] = make_float2(hi_(acc[0][bp])+e0, hi_(acc[1][bp])+e1);
  }
}

// ---------------- encoder recurrent GEMM: h @ enc_wh -> gpart ----------------
__global__ void k_enc_gemm(const float* __restrict__ wh){
  __shared__ float2 sh2[16][64];
  int tid = threadIdx.x;
  int ks = blockIdx.x & 15;
  int colbase = (blockIdx.x >> 4)*128;
  int kb = ks*64;
  int cl = tid & 63, bg = tid >> 6;
  u64 acc[2][4] = {};
  #pragma unroll
  for (int r=0;r<4;r++){
    int idx=tid+r*256; int bp=idx>>6, kk=idx&63;
    sh2[bp][kk] = make_float2(d_h[(2*bp)*H + kb+kk], d_h[(2*bp+1)*H + kb+kk]);
  }
  __syncthreads();
  #pragma unroll 8
  for (int kk=0;kk<64;kk++){
    float2 w = *(const float2*)(wh + (size_t)(kb+kk)*G4 + colbase + 2*cl);
    u64 wa = bcast_f(w.x), wb = bcast_f(w.y);
    #pragma unroll
    for (int bp=0;bp<4;bp++){
      u64 a = *(const u64*)&sh2[bg*4+bp][kk];
      fma2(acc[0][bp],a,wa); fma2(acc[1][bp],a,wb);
    }
  }
  int c0 = colbase + 2*cl;
  #pragma unroll
  for (int bp=0;bp<4;bp++){
    int b0 = bg*8 + 2*bp;
    *(float2*)&d_gpart[ks][b0][c0]   = make_float2(lo_(acc[0][bp]), lo_(acc[1][bp]));
    *(float2*)&d_gpart[ks][b0+1][c0] = make_float2(hi_(acc[0][bp]), hi_(acc[1][bp]));
  }
}

// ---------------- encoder pointwise ----------------
__global__ void k_enc_point(int t){
  int idx = blockIdx.x*256 + threadIdx.x;
  int b = idx >> 10, j = idx & 1023;
  float g0 = d_xg[t][b][j],      g1 = d_xg[t][b][j+1024];
  float g2 = d_xg[t][b][j+2048], g3 = d_xg[t][b][j+3072];
  #pragma unroll
  for (int p=0;p<16;p++){
    g0 += d_gpart[p][b][j];      g1 += d_gpart[p][b][j+1024];
    g2 += d_gpart[p][b][j+2048]; g3 += d_gpart[p][b][j+3072];
  }
  float c = d_c[idx];
  c = sigmoidf_(g1)*c + sigmoidf_(g0)*tanhf(g2);
  float h = sigmoidf_(g3)*tanhf(c);
  d_c[idx]=c; d_h[idx]=h;
  d_encouts[(b*L + t)*H + j] = h;
}

// ---------------- attention phase 1: logit partials (+ e materialization) -------------
// grid 256 = 32 b x 8 ks (256 K each)
__global__ void k_attn1(const float* __restrict__ demb, const float* __restrict__ aw_w){
  __shared__ float sp[256];
  int b = blockIdx.x >> 3, ks = blockIdx.x & 7;
  int tid = threadIdx.x;
  int tok = d_tok[b];
  const float* erow = demb + (size_t)tok*H;
  if (ks < 4) d_e[b*H + ks*256 + tid] = erow[ks*256 + tid];
  int col = tid & 63, kg = tid >> 6;
  int k0 = ks*256 + kg*64;
  float acc = 0.f;
  const float* arow = (k0 < H) ? (erow + k0) : (d_h + b*H + (k0-H));
  #pragma unroll 4
  for (int i=0;i<64;i++) acc += arow[i] * aw_w[(size_t)(k0+i)*64 + col];
  sp[tid] = acc;
  __syncthreads();
  if (tid < 64) d_apart[ks][b][tid] = sp[tid] + sp[tid+64] + sp[tid+128] + sp[tid+192];
}

// ---------------- attention phase 2: softmax + context ----------------
// grid 128 = 32 b x 4 jblk (256 j each)
__global__ void k_attn_ctx(const float* __restrict__ ab){
  __shared__ float s_aw[64];
  __shared__ float s_red[2];
  int b = blockIdx.x >> 2, jblk = blockIdx.x & 3;
  int tid = threadIdx.x;
  if (tid < 64){
    float lg = ab[tid];
    #pragma unroll
    for (int p=0;p<8;p++) lg += d_apart[p][b][tid];
    s_aw[tid] = lg;
  }
  __syncthreads();
  if (tid < 32){
    float m = fmaxf(s_aw[tid], s_aw[tid+32]);
    #pragma unroll
    for (int o=16;o>0;o>>=1) m = fmaxf(m, __shfl_xor_sync(0xffffffffu, m, o));
    if (tid==0) s_red[0]=m;
  }
  __syncthreads();
  if (tid < 64) s_aw[tid] = expf(s_aw[tid] - s_red[0]);
  __syncthreads();
  if (tid < 32){
    float s = s_aw[tid] + s_aw[tid+32];
    #pragma unroll
    for (int o=16;o>0;o>>=1) s += __shfl_xor_sync(0xffffffffu, s, o);
    if (tid==0) s_red[1]=s;
  }
  __syncthreads();
  float inv = 1.f / s_red[1];
  int j = jblk*256 + tid;
  float c = 0.f;
  #pragma unroll 4
  for (int l=0;l<64;l++) c += s_aw[l]*inv * d_encouts[(b*L + l)*H + j];
  d_ctx[b*H + j] = c;
}

// ---------------- combine GEMM: concat(e,ctx) @ comb_w -> cpart ----------------
__global__ void k_dec_comb(const float* __restrict__ w){
  __shared__ float2 sh2[16][64];
  int tid = threadIdx.x;
  int ks = blockIdx.x & 15;
  int colbase = (blockIdx.x >> 4)*128;
  int cl = tid & 63, bg = tid >> 6;
  u64 acc[2][4] = {};
  for (int kc=0;kc<2;kc++){
    int kb = ks*128 + kc*64;
    #pragma unroll
    for (int r=0;r<4;r++){
      int idx=tid+r*256; int bp=idx>>6, kk=idx&63; int k = kb+kk;
      float a0,a1;
      if (k < H){ a0 = d_e[(2*bp)*H + k];       a1 = d_e[(2*bp+1)*H + k]; }
      else      { a0 = d_ctx[(2*bp)*H + (k-H)]; a1 = d_ctx[(2*bp+1)*H + (k-H)]; }
      sh2[bp][kk] = make_float2(a0, a1);
    }
    __syncthreads();
    #pragma unroll 8
    for (int kk=0;kk<64;kk++){
      float2 wv = *(const float2*)(w + (size_t)(kb+kk)*H + colbase + 2*cl);
      u64 wa = bcast_f(wv.x), wb = bcast_f(wv.y);
      #pragma unroll
      for (int bp=0;bp<4;bp++){
        u64 a = *(const u64*)&sh2[bg*4+bp][kk];
        fma2(acc[0][bp],a,wa); fma2(acc[1][bp],a,wb);
      }
    }
    __syncthreads();
  }
  int c0 = colbase + 2*cl;
  #pragma unroll
  for (int bp=0;bp<4;bp++){
    int b0 = bg*8 + 2*bp;
    *(float2*)&d_cpart[ks][b0][c0]   = make_float2(lo_(acc[0][bp]), lo_(acc[1][bp]));
    *(float2*)&d_cpart[ks][b0+1][c0] = make_float2(hi_(acc[0][bp]), hi_(acc[1][bp]));
  }
}

// ---------------- combine finalize ----------------
__global__ void k_combfin(const float* __restrict__ cb){
  int idx = blockIdx.x*256 + threadIdx.x;
  int b = idx >> 10, j = idx & 1023;
  float s = cb[j];
  #pragma unroll
  for (int p=0;p<16;p++) s += d_cpart[p][b][j];
  d_cin[idx] = fmaxf(s, 0.f);
}

// ---------------- decoder gates GEMM ----------------
__global__ void k_dec_gates(const float* __restrict__ wx, const float* __restrict__ wh){
  __shared__ float2 sh2[16][64];
  int tid = threadIdx.x;
  int ks = blockIdx.x & 15;
  int colbase = (blockIdx.x >> 4)*128;
  int cl = tid & 63, bg = tid >> 6;
  u64 acc[2][4] = {};
  for (int kc=0;kc<2;kc++){
    int kb = ks*128 + kc*64;
    #pragma unroll
    for (int r=0;r<4;r++){
      int idx=tid+r*256; int bp=idx>>6, kk=idx&63; int k = kb+kk;
      float a0,a1;
      if (k < H){ a0 = d_cin[(2*bp)*H + k];   a1 = d_cin[(2*bp+1)*H + k]; }
      else      { a0 = d_h[(2*bp)*H + (k-H)]; a1 = d_h[(2*bp+1)*H + (k-H)]; }
      sh2[bp][kk] = make_float2(a0, a1);
    }
    __syncthreads();
    const float* Wb = (kb < H) ? (wx + (size_t)kb*G4) : (wh + (size_t)(kb-H)*G4);
    #pragma unroll 8
    for (int kk=0;kk<64;kk++){
      float2 wv = *(const float2*)(Wb + (size_t)kk*G4 + colbase + 2*cl);
      u64 wa = bcast_f(wv.x), wb2 = bcast_f(wv.y);
      #pragma unroll
      for (int bp=0;bp<4;bp++){
        u64 a = *(const u64*)&sh2[bg*4+bp][kk];
        fma2(acc[0][bp],a,wa); fma2(acc[1][bp],a,wb2);
      }
    }
    __syncthreads();
  }
  int c0 = colbase + 2*cl;
  #pragma unroll
  for (int bp=0;bp<4;bp++){
    int b0 = bg*8 + 2*bp;
    *(float2*)&d_gpart[ks][b0][c0]   = make_float2(lo_(acc[0][bp]), lo_(acc[1][bp]));
    *(float2*)&d_gpart[ks][b0+1][c0] = make_float2(hi_(acc[0][bp]), hi_(acc[1][bp]));
  }
}

// ---------------- decoder pointwise ----------------
__global__ void k_dec_point(const float* __restrict__ db){
  int idx = blockIdx.x*256 + threadIdx.x;
  int b = idx >> 10, j = idx & 1023;
  float g0 = db[j], g1 = db[j+1024], g2 = db[j+2048], g3 = db[j+3072];
  #pragma unroll
  for (int p=0;p<16;p++){
    g0 += d_gpart[p][b][j];      g1 += d_gpart[p][b][j+1024];
    g2 += d_gpart[p][b][j+2048]; g3 += d_gpart[p][b][j+3072];
  }
  float c = d_c[idx];
  c = sigmoidf_(g1)*c + sigmoidf_(g0)*tanhf(g2);
  float h = sigmoidf_(g3)*tanhf(c);
  d_c[idx]=c; d_h[idx]=h;
}

// ---------------- logits via mma.sync bf16: D[32 x 128] = h @ owT^T ----------------
// grid 250 (128 vocab cols each); 256 threads = 8 warps (warp w: cols w*16..w*16+15)
// A (h->bf16) staged per-128K-chunk in smem; B fragments straight from d_owT (K-contig).
__global__ void k_logits_mma(const float* __restrict__ ob, float* __restrict__ out, int t){
  __shared__ u32 sA[32][68];        // padded: bank = 4*row + word (conflict-free)
  __shared__ float sLg[32][132];
  int tid = threadIdx.x, wid = tid>>5, lane = tid&31;
  int colbase = blockIdx.x*128;
  int g = lane>>2, q = lane&3;
  float acc[2][2][4];
  #pragma unroll
  for (int m=0;m<2;m++)
    #pragma unroll
    for (int j=0;j<2;j++)
      #pragma unroll
      for (int r=0;r<4;r++) acc[m][j][r]=0.f;

  const u32* wp = d_owT + (size_t)(colbase + wid*16 + g)*512 + q;

  for (int kc=0;kc<8;kc++){
    // stage A: rows=batch, 64 bf16-pair words for K chunk [kc*128, +128)
    {
      int row = tid>>3, w0 = (tid&7)*8;
      const float2* hp = (const float2*)(d_h + row*H + kc*128) + w0;
      #pragma unroll
      for (int i=0;i<8;i++){
        float2 v = hp[i];
        sA[row][w0+i] = (f2bf(v.y)<<16) | f2bf(v.x);
      }
    }
    __syncthreads();
    const u32* wkc = wp + kc*64;
    #pragma unroll
    for (int ks=0;ks<8;ks++){
      int kw = ks*8;
      u32 a00 = sA[g   ][kw+q], a10 = sA[g+8 ][kw+q];
      u32 a20 = sA[g   ][kw+4+q], a30 = sA[g+8 ][kw+4+q];
      u32 a01 = sA[g+16][kw+q], a11 = sA[g+24][kw+q];
      u32 a21 = sA[g+16][kw+4+q], a31 = sA[g+24][kw+4+q];
      #pragma unroll
      for (int j=0;j<2;j++){
        u32 b0 = wkc[j*8*512 + kw];
        u32 b1 = wkc[j*8*512 + kw + 4];
        mma_bf16(acc[0][j], a00,a10,a20,a30, b0,b1);
        mma_bf16(acc[1][j], a01,a11,a21,a31, b0,b1);
      }
    }
    __syncthreads();
  }
  // accumulators -> smem
  #pragma unroll
  for (int m=0;m<2;m++)
    #pragma unroll
    for (int j=0;j<2;j++){
      int col = wid*16 + j*8 + q*2;
      *(float2*)&sLg[g + m*16    ][col] = make_float2(acc[m][j][0], acc[m][j][1]);
      *(float2*)&sLg[g + m*16 + 8][col] = make_float2(acc[m][j][2], acc[m][j][3]);
    }
  __syncthreads();
  // epilogue: warp w owns batch rows 4w..4w+3; +bias, store, stats
  const float* bp = ob + colbase;
  float4 bb = *(const float4*)(bp + lane*4);
  #pragma unroll
  for (int rr=0;rr<4;rr++){
    int b = wid*4 + rr;
    int c0 = lane*4;
    float4 v = *(float4*)&sLg[b][c0];
    v.x += bb.x; v.y += bb.y; v.z += bb.z; v.w += bb.w;
    float* orow = out + ((size_t)(b*L + t))*V + colbase;
    *(float4*)(orow + c0) = v;
    float m = v.x; int mi = c0;
    if (v.y > m){ m=v.y; mi=c0+1; }
    if (v.z > m){ m=v.z; mi=c0+2; }
    if (v.w > m){ m=v.w; mi=c0+3; }
    #pragma unroll
    for (int o=16;o>0;o>>=1){
      float om = __shfl_xor_sync(0xffffffffu, m, o);
      int   oi = __shfl_xor_sync(0xffffffffu, mi, o);
      if (om > m || (om == m && oi < mi)){ m=om; mi=oi; }
    }
    float S = expf(v.x-m)+expf(v.y-m)+expf(v.z-m)+expf(v.w-m);
    #pragma unroll
    for (int o=16;o>0;o>>=1) S += __shfl_xor_sync(0xffffffffu, S, o);
    if (lane == 0){
      d_lm2[b*250 + blockIdx.x] = m;
      d_ls2[b*250 + blockIdx.x] = S;
      d_li2[b*250 + blockIdx.x] = colbase + mi;
    }
  }
}

// ---------------- final: combine stats, subtract lse, emit token ----------------
// grid 512 = 32 b x 16 vchunk(2000)
__global__ void k_lsm2(float* __restrict__ out, int t){
  __shared__ float sm[256]; __shared__ int si[256]; __shared__ float ssum[256];
  int b = blockIdx.x & 31, ch = blockIdx.x >> 5;
  int tid = threadIdx.x;
  float m = -INFINITY; int mi = 0x7fffffff;
  if (tid < 250){ m = d_lm2[b*250+tid]; mi = d_li2[b*250+tid]; }
  sm[tid]=m; si[tid]=mi;
  __syncthreads();
  for (int s=128;s>0;s>>=1){
    if (tid < s){
      float om=sm[tid+s]; int oi=si[tid+s];
      if (om > sm[tid] || (om == sm[tid] && oi < si[tid])){ sm[tid]=om; si[tid]=oi; }
    }
    __syncthreads();
  }
  float M = sm[0];
  float se = (tid < 250) ? d_ls2[b*250+tid]*expf(d_lm2[b*250+tid] - M) : 0.f;
  ssum[tid]=se; __syncthreads();
  for (int s=128;s>0;s>>=1){ if (tid<s) ssum[tid]+=ssum[tid+s]; __syncthreads(); }
  float lse = M + logf(ssum[0]);
  if (ch==0 && tid==0) d_tok[b] = si[0];
  float* row = out + (size_t)(b*L + t)*V + ch*2000;
  for (int v = tid; v < 2000; v += 256) row[v] -= lse;
}

// ---------------- launcher ----------------
extern "C" void kernel_launch(void* const* d_in, const int* in_sizes, int n_in,
                              void* d_out, int out_size){
  const int*   x         = (const int*)  d_in[0];
  const float* enc_embed = (const float*)d_in[1];
  const float* enc_wx    = (const float*)d_in[2];
  const float* enc_wh    = (const float*)d_in[3];
  const float* enc_b     = (const float*)d_in[4];
  const float* dec_embed = (const float*)d_in[5];
  const float* attn_w    = (const float*)d_in[6];
  const float* attn_b    = (const float*)d_in[7];
  const float* comb_w    = (const float*)d_in[8];
  const float* comb_b    = (const float*)d_in[9];
  const float* dec_wx    = (const float*)d_in[10];
  const float* dec_wh    = (const float*)d_in[11];
  const float* dec_b     = (const float*)d_in[12];
  const float* out_w     = (const float*)d_in[13];
  const float* out_b     = (const float*)d_in[14];
  float* out = (float*)d_out;

  k_init<<<128,256>>>();
  k_conv_owT<<<8000,256>>>(out_w);
  k_xg<<<2048,256>>>(x, enc_embed, enc_wx, enc_b);
  for (int t=0;t<64;t++){
    k_enc_gemm<<<512,256>>>(enc_wh);
    k_enc_point<<<128,256>>>(t);
  }
  k_init<<<128,256>>>();
  for (int t=0;t<64;t++){
    k_attn1<<<256,256>>>(dec_embed, attn_w);
    k_attn_ctx<<<128,256>>>(attn_b);
    k_dec_comb<<<128,256>>>(comb_w);
    k_combfin<<<128,256>>>(comb_b);
    k_dec_gates<<<512,256>>>(dec_wx, dec_wh);
    k_dec_point<<<128,256>>>(dec_b);
    k_logits_mma<<<250,256>>>(out_b, out, t);
    k_lsm2<<<512,256>>>(out, t);
  }
}

// round 8
// speedup vs baseline: 4.1189x; 1.2867x over previous
#include <cuda_runtime.h>
#include <math.h>
#include <stdint.h>

#define B 32
#define L 64
#define E 512
#define H 1024
#define G4 4096
#define V 32000

typedef unsigned int u32;
typedef unsigned long long u64;

// ---------------- scratch state (device globals; no allocs) ----------------
__device__ float d_h[B*H];
__device__ float d_c[B*H];
__device__ float d_encouts[B*L*H];       // [b][l][j]
__device__ float d_xg[L][B][G4];         // precomputed emb@enc_wx + enc_b
__device__ float d_gpart[8][B][G4];      // K-split partials for gate GEMMs
__device__ float d_cpart[8][B][H];       // K-split partials for combine GEMM
__device__ float d_cin[B*H];             // relu(combine)
__device__ float d_e[B*H];               // decoder embedding of current token
__device__ float d_ctx[B*H];             // attention context
__device__ float d_apart[8][B][64];      // attention logit partials
__device__ int   d_tok[B];
__device__ u32   d_owT[(size_t)V*512];   // out_w^T    [V][512]  bf16-pairs (64MB)
__device__ u32   d_whT[(size_t)G4*512];  // enc_wh^T   [4096][512]  (8MB)
__device__ u32   d_gwT[(size_t)G4*1024]; // [dec_wx;dec_wh]^T [4096][1024] (16MB)
__device__ u32   d_cwT[(size_t)H*1024];  // comb_w^T   [1024][1024] (4MB)
__device__ float d_lm2[B*250];           // per-(b,colchunk) max
__device__ float d_ls2[B*250];           // per-(b,colchunk) expsum
__device__ int   d_li2[B*250];           // per-(b,colchunk) argmax

__device__ __forceinline__ float sigmoidf_(float x){ return 1.f/(1.f+expf(-x)); }
__device__ __forceinline__ u64 bcast_f(float x){ u64 r; asm("mov.b64 %0,{%1,%1};" : "=l"(r) : "f"(x)); return r; }
__device__ __forceinline__ void fma2(u64& d, u64 a, u64 b){ asm("fma.rn.f32x2 %0,%1,%2,%0;" : "+l"(d) : "l"(a), "l"(b)); }
__device__ __forceinline__ float lo_(u64 v){ return __uint_as_float((u32)v); }
__device__ __forceinline__ float hi_(u64 v){ return __uint_as_float((u32)(v>>32)); }
__device__ __forceinline__ u32 f2bf(float f){ u32 b=__float_as_uint(f); return (b + 0x7fffu + ((b>>16)&1u))>>16; }

// classic tensor-core mma (sm_80+, suffix-free PTX -> compiles for sm_103)
__device__ __forceinline__ void mma_bf16(float* d, u32 a0,u32 a1,u32 a2,u32 a3,u32 b0,u32 b1){
  asm volatile("mma.sync.aligned.m16n8k16.row.col.f32.bf16.bf16.f32 "
    "{%0,%1,%2,%3}, {%4,%5,%6,%7}, {%8,%9}, {%0,%1,%2,%3};"
    : "+f"(d[0]),"+f"(d[1]),"+f"(d[2]),"+f"(d[3])
    : "r"(a0),"r"(a1),"r"(a2),"r"(a3),"r"(b0),"r"(b1));
}

// ---------------- init ----------------
__global__ void k_init(){
  int idx = blockIdx.x*256 + threadIdx.x;
  if (idx < B*H){ d_h[idx]=0.f; d_c[idx]=0.f; }
  if (idx < B) d_tok[idx] = 127;
}

// ---------------- one-time generic transpose-convert ----------------
// src fp32 [K][N] (row stride ns) -> dst u32 [N][kt] bf16-pairs at word offset k0w
// grid = nblks * (K/64); 256 threads
__global__ void k_T(const float* __restrict__ src, int ns, u32* __restrict__ dst,
                    int kt, int k0w, int nblks){
  __shared__ float sh[64][65];
  int nb = blockIdx.x % nblks, kb = blockIdx.x / nblks;
  int n0 = nb*64, k0 = kb*64;
  int tid = threadIdx.x;
  int nc = tid & 63, kg = tid >> 6;
  #pragma unroll
  for (int r=0;r<16;r++){
    int kr = kg*16 + r;
    sh[kr][nc] = src[(size_t)(k0+kr)*ns + n0 + nc];
  }
  __syncthreads();
  int nl = tid >> 2, p0 = (tid & 3)*8;
  u32* d = dst + (size_t)(n0+nl)*kt + k0w + (k0>>1);
  #pragma unroll
  for (int q=0;q<8;q++){
    int p = p0 + q;
    d[p] = (f2bf(sh[2*p+1][nl])<<16) | f2bf(sh[2*p][nl]);
  }
}

// ---------------- one-time: xg[t] = emb(x_t) @ enc_wx + enc_b ----------------
__global__ void k_xg(const int* __restrict__ x, const float* __restrict__ emb,
                     const float* __restrict__ wx, const float* __restrict__ eb){
  __shared__ float2 sh2[16][64];
  int tid = threadIdx.x;
  int t = blockIdx.x >> 5;
  int colbase = (blockIdx.x & 31)*128;
  int cl = tid & 63, bg = tid >> 6;
  u64 acc[2][4] = {};
  for (int kc=0;kc<8;kc++){
    int kb = kc*64;
    #pragma unroll
    for (int r=0;r<4;r++){
      int idx=tid+r*256; int bp=idx>>6, kk=idx&63; int k = kb+kk;
      sh2[bp][kk] = make_float2(emb[(size_t)x[(2*bp)*L+t]*E + k],
                                emb[(size_t)x[(2*bp+1)*L+t]*E + k]);
    }
    __syncthreads();
    #pragma unroll 8
    for (int kk=0;kk<64;kk++){
      float2 w = *(const float2*)(wx + (size_t)(kb+kk)*G4 + colbase + 2*cl);
      u64 wa = bcast_f(w.x), wb = bcast_f(w.y);
      #pragma unroll
      for (int bp=0;bp<4;bp++){
        u64 a = *(const u64*)&sh2[bg*4+bp][kk];
        fma2(acc[0][bp],a,wa); fma2(acc[1][bp],a,wb);
      }
    }
    __syncthreads();
  }
  int c0 = colbase + 2*cl;
  float e0 = eb[c0], e1 = eb[c0+1];
  #pragma unroll
  for (int bp=0;bp<4;bp++){
    int b0 = bg*8 + 2*bp;
    *(float2*)&d_xg[t][b0][c0]   = make_float2(lo_(acc[0][bp])+e0, lo_(acc[1][bp])+e1);
    *(float2*)&d_xg[t][b0+1][c0] = make_float2(hi_(acc[0][bp])+e0, hi_(acc[1][bp])+e1);
  }
}

// ---------------- generic bf16 mma GEMM: P[32 x 128cols] partials ----------------
// mode 0: enc gates  A=h            wT=d_whT kt=512  chunks=1 out=d_gpart stride G4
// mode 1: dec gates  A=cin|h        wT=d_gwT kt=1024 chunks=2 out=d_gpart stride G4
// mode 2: combine    A=e|ctx        wT=d_cwT kt=1024 chunks=2 out=d_cpart stride H
// grid = ncolblk*8 (ks = blockIdx.x & 7); 256 threads = 8 warps x 16 cols
__global__ void k_mm_bf16(int mode){
  __shared__ u32 sA[32][68];
  __shared__ float sO[32][132];
  int tid = threadIdx.x, wid = tid>>5, lane = tid&31;
  int ks = blockIdx.x & 7;
  int colbase = (blockIdx.x >> 3)*128;
  int g = lane>>2, q = lane&3;
  const u32* wT; int kt, chunks; float* outp; int ostride;
  if (mode == 0){ wT = d_whT; kt = 512;  chunks = 1; outp = &d_gpart[0][0][0]; ostride = G4; }
  else if (mode == 1){ wT = d_gwT; kt = 1024; chunks = 2; outp = &d_gpart[0][0][0]; ostride = G4; }
  else { wT = d_cwT; kt = 1024; chunks = 2; outp = &d_cpart[0][0][0]; ostride = H; }

  float acc[2][2][4] = {};
  const u32* wp = wT + (size_t)(colbase + wid*16 + g)*kt + q;

  for (int kc=0; kc<chunks; kc++){
    int kb = (ks*chunks + kc)*128;
    {
      int row = tid>>3, w0 = (tid&7)*8;
      int kg0 = kb + w0*2;
      const float* src;
      if (mode == 0)      src = d_h + row*H + kg0;
      else if (mode == 1) src = (kb < H) ? (d_cin + row*H + kg0) : (d_h + row*H + kg0 - H);
      else                src = (kb < H) ? (d_e  + row*H + kg0) : (d_ctx + row*H + kg0 - H);
      const float2* hp = (const float2*)src;
      #pragma unroll
      for (int i=0;i<8;i++){
        float2 v = hp[i];
        sA[row][w0+i] = (f2bf(v.y)<<16) | f2bf(v.x);
      }
    }
    __syncthreads();
    const u32* wkc = wp + (ks*chunks + kc)*64;
    #pragma unroll
    for (int kss=0;kss<8;kss++){
      int kw = kss*8;
      u32 a00 = sA[g   ][kw+q],   a10 = sA[g+8 ][kw+q];
      u32 a20 = sA[g   ][kw+4+q], a30 = sA[g+8 ][kw+4+q];
      u32 a01 = sA[g+16][kw+q],   a11 = sA[g+24][kw+q];
      u32 a21 = sA[g+16][kw+4+q], a31 = sA[g+24][kw+4+q];
      #pragma unroll
      for (int j=0;j<2;j++){
        u32 b0 = wkc[(size_t)j*8*kt + kw];
        u32 b1 = wkc[(size_t)j*8*kt + kw + 4];
        mma_bf16(acc[0][j], a00,a10,a20,a30, b0,b1);
        mma_bf16(acc[1][j], a01,a11,a21,a31, b0,b1);
      }
    }
    __syncthreads();
  }
  #pragma unroll
  for (int m=0;m<2;m++)
    #pragma unroll
    for (int j=0;j<2;j++){
      int col = wid*16 + j*8 + q*2;
      *(float2*)&sO[g + m*16    ][col] = make_float2(acc[m][j][0], acc[m][j][1]);
      *(float2*)&sO[g + m*16 + 8][col] = make_float2(acc[m][j][2], acc[m][j][3]);
    }
  __syncthreads();
  #pragma unroll
  for (int rr=0;rr<4;rr++){
    int b = wid*4 + rr;
    int c0 = lane*4;
    float4 v = *(float4*)&sO[b][c0];
    *(float4*)(outp + (size_t)(ks*B + b)*ostride + colbase + c0) = v;
  }
}

// ---------------- encoder pointwise ----------------
__global__ void k_enc_point(int t){
  int idx = blockIdx.x*256 + threadIdx.x;
  int b = idx >> 10, j = idx & 1023;
  float g0 = d_xg[t][b][j],      g1 = d_xg[t][b][j+1024];
  float g2 = d_xg[t][b][j+2048], g3 = d_xg[t][b][j+3072];
  #pragma unroll
  for (int p=0;p<8;p++){
    g0 += d_gpart[p][b][j];      g1 += d_gpart[p][b][j+1024];
    g2 += d_gpart[p][b][j+2048]; g3 += d_gpart[p][b][j+3072];
  }
  float c = d_c[idx];
  c = sigmoidf_(g1)*c + sigmoidf_(g0)*tanhf(g2);
  float h = sigmoidf_(g3)*tanhf(c);
  d_c[idx]=c; d_h[idx]=h;
  d_encouts[(b*L + t)*H + j] = h;
}

// ---------------- attention phase 1: logit partials (+ e materialization) -------------
// grid 256 = 32 b x 8 ks (256 K each)
__global__ void k_attn1(const float* __restrict__ demb, const float* __restrict__ aw_w){
  __shared__ float sp[256];
  int b = blockIdx.x >> 3, ks = blockIdx.x & 7;
  int tid = threadIdx.x;
  int tok = d_tok[b];
  const float* erow = demb + (size_t)tok*H;
  if (ks < 4) d_e[b*H + ks*256 + tid] = erow[ks*256 + tid];
  int col = tid & 63, kg = tid >> 6;
  int k0 = ks*256 + kg*64;
  float acc = 0.f;
  const float* arow = (k0 < H) ? (erow + k0) : (d_h + b*H + (k0-H));
  #pragma unroll 4
  for (int i=0;i<64;i++) acc += arow[i] * aw_w[(size_t)(k0+i)*64 + col];
  sp[tid] = acc;
  __syncthreads();
  if (tid < 64) d_apart[ks][b][tid] = sp[tid] + sp[tid+64] + sp[tid+128] + sp[tid+192];
}

// ---------------- attention phase 2: softmax + context ----------------
// grid 128 = 32 b x 4 jblk (256 j each)
__global__ void k_attn_ctx(const float* __restrict__ ab){
  __shared__ float s_aw[64];
  __shared__ float s_red[2];
  int b = blockIdx.x >> 2, jblk = blockIdx.x & 3;
  int tid = threadIdx.x;
  if (tid < 64){
    float lg = ab[tid];
    #pragma unroll
    for (int p=0;p<8;p++) lg += d_apart[p][b][tid];
    s_aw[tid] = lg;
  }
  __syncthreads();
  if (tid < 32){
    float m = fmaxf(s_aw[tid], s_aw[tid+32]);
    #pragma unroll
    for (int o=16;o>0;o>>=1) m = fmaxf(m, __shfl_xor_sync(0xffffffffu, m, o));
    if (tid==0) s_red[0]=m;
  }
  __syncthreads();
  if (tid < 64) s_aw[tid] = expf(s_aw[tid] - s_red[0]);
  __syncthreads();
  if (tid < 32){
    float s = s_aw[tid] + s_aw[tid+32];
    #pragma unroll
    for (int o=16;o>0;o>>=1) s += __shfl_xor_sync(0xffffffffu, s, o);
    if (tid==0) s_red[1]=s;
  }
  __syncthreads();
  float inv = 1.f / s_red[1];
  int j = jblk*256 + tid;
  float c = 0.f;
  #pragma unroll 4
  for (int l=0;l<64;l++) c += s_aw[l]*inv * d_encouts[(b*L + l)*H + j];
  d_ctx[b*H + j] = c;
}

// ---------------- combine finalize ----------------
__global__ void k_combfin(const float* __restrict__ cb){
  int idx = blockIdx.x*256 + threadIdx.x;
  int b = idx >> 10, j = idx & 1023;
  float s = cb[j];
  #pragma unroll
  for (int p=0;p<8;p++) s += d_cpart[p][b][j];
  d_cin[idx] = fmaxf(s, 0.f);
}

// ---------------- decoder pointwise ----------------
__global__ void k_dec_point(const float* __restrict__ db){
  int idx = blockIdx.x*256 + threadIdx.x;
  int b = idx >> 10, j = idx & 1023;
  float g0 = db[j], g1 = db[j+1024], g2 = db[j+2048], g3 = db[j+3072];
  #pragma unroll
  for (int p=0;p<8;p++){
    g0 += d_gpart[p][b][j];      g1 += d_gpart[p][b][j+1024];
    g2 += d_gpart[p][b][j+2048]; g3 += d_gpart[p][b][j+3072];
  }
  float c = d_c[idx];
  c = sigmoidf_(g1)*c + sigmoidf_(g0)*tanhf(g2);
  float h = sigmoidf_(g3)*tanhf(c);
  d_c[idx]=c; d_h[idx]=h;
}

// ---------------- logits via mma.sync bf16: D[32 x 128] = h @ owT^T ----------------
// grid 250 (128 vocab cols each); 256 threads = 8 warps (warp w: cols w*16..w*16+15)
__global__ void k_logits_mma(const float* __restrict__ ob, float* __restrict__ out, int t){
  __shared__ u32 sA[32][68];
  __shared__ float sLg[32][132];
  int tid = threadIdx.x, wid = tid>>5, lane = tid&31;
  int colbase = blockIdx.x*128;
  int g = lane>>2, q = lane&3;
  float acc[2][2][4];
  #pragma unroll
  for (int m=0;m<2;m++)
    #pragma unroll
    for (int j=0;j<2;j++)
      #pragma unroll
      for (int r=0;r<4;r++) acc[m][j][r]=0.f;

  const u32* wp = d_owT + (size_t)(colbase + wid*16 + g)*512 + q;

  for (int kc=0;kc<8;kc++){
    {
      int row = tid>>3, w0 = (tid&7)*8;
      const float2* hp = (const float2*)(d_h + row*H + kc*128) + w0;
      #pragma unroll
      for (int i=0;i<8;i++){
        float2 v = hp[i];
        sA[row][w0+i] = (f2bf(v.y)<<16) | f2bf(v.x);
      }
    }
    __syncthreads();
    const u32* wkc = wp + kc*64;
    #pragma unroll
    for (int ks=0;ks<8;ks++){
      int kw = ks*8;
      u32 a00 = sA[g   ][kw+q], a10 = sA[g+8 ][kw+q];
      u32 a20 = sA[g   ][kw+4+q], a30 = sA[g+8 ][kw+4+q];
      u32 a01 = sA[g+16][kw+q], a11 = sA[g+24][kw+q];
      u32 a21 = sA[g+16][kw+4+q], a31 = sA[g+24][kw+4+q];
      #pragma unroll
      for (int j=0;j<2;j++){
        u32 b0 = wkc[j*8*512 + kw];
        u32 b1 = wkc[j*8*512 + kw + 4];
        mma_bf16(acc[0][j], a00,a10,a20,a30, b0,b1);
        mma_bf16(acc[1][j], a01,a11,a21,a31, b0,b1);
      }
    }
    __syncthreads();
  }
  #pragma unroll
  for (int m=0;m<2;m++)
    #pragma unroll
    for (int j=0;j<2;j++){
      int col = wid*16 + j*8 + q*2;
      *(float2*)&sLg[g + m*16    ][col] = make_float2(acc[m][j][0], acc[m][j][1]);
      *(float2*)&sLg[g + m*16 + 8][col] = make_float2(acc[m][j][2], acc[m][j][3]);
    }
  __syncthreads();
  const float* bp = ob + colbase;
  float4 bb = *(const float4*)(bp + lane*4);
  #pragma unroll
  for (int rr=0;rr<4;rr++){
    int b = wid*4 + rr;
    int c0 = lane*4;
    float4 v = *(float4*)&sLg[b][c0];
    v.x += bb.x; v.y += bb.y; v.z += bb.z; v.w += bb.w;
    float* orow = out + ((size_t)(b*L + t))*V + colbase;
    *(float4*)(orow + c0) = v;
    float m = v.x; int mi = c0;
    if (v.y > m){ m=v.y; mi=c0+1; }
    if (v.z > m){ m=v.z; mi=c0+2; }
    if (v.w > m){ m=v.w; mi=c0+3; }
    #pragma unroll
    for (int o=16;o>0;o>>=1){
      float om = __shfl_xor_sync(0xffffffffu, m, o);
      int   oi = __shfl_xor_sync(0xffffffffu, mi, o);
      if (om > m || (om == m && oi < mi)){ m=om; mi=oi; }
    }
    float S = expf(v.x-m)+expf(v.y-m)+expf(v.z-m)+expf(v.w-m);
    #pragma unroll
    for (int o=16;o>0;o>>=1) S += __shfl_xor_sync(0xffffffffu, S, o);
    if (lane == 0){
      d_lm2[b*250 + blockIdx.x] = m;
      d_ls2[b*250 + blockIdx.x] = S;
      d_li2[b*250 + blockIdx.x] = colbase + mi;
    }
  }
}

// ---------------- final: combine stats, subtract lse, emit token ----------------
// grid 512 = 32 b x 16 vchunk(2000)
__global__ void k_lsm2(float* __restrict__ out, int t){
  __shared__ float sm[256]; __shared__ int si[256]; __shared__ float ssum[256];
  int b = blockIdx.x & 31, ch = blockIdx.x >> 5;
  int tid = threadIdx.x;
  float m = -INFINITY; int mi = 0x7fffffff;
  if (tid < 250){ m = d_lm2[b*250+tid]; mi = d_li2[b*250+tid]; }
  sm[tid]=m; si[tid]=mi;
  __syncthreads();
  for (int s=128;s>0;s>>=1){
    if (tid < s){
      float om=sm[tid+s]; int oi=si[tid+s];
      if (om > sm[tid] || (om == sm[tid] && oi < si[tid])){ sm[tid]=om; si[tid]=oi; }
    }
    __syncthreads();
  }
  float M = sm[0];
  float se = (tid < 250) ? d_ls2[b*250+tid]*expf(d_lm2[b*250+tid] - M) : 0.f;
  ssum[tid]=se; __syncthreads();
  for (int s=128;s>0;s>>=1){ if (tid<s) ssum[tid]+=ssum[tid+s]; __syncthreads(); }
  float lse = M + logf(ssum[0]);
  if (ch==0 && tid==0) d_tok[b] = si[0];
  float* row = out + (size_t)(b*L + t)*V + ch*2000;
  for (int v = tid; v < 2000; v += 256) row[v] -= lse;
}

// ---------------- launcher ----------------
extern "C" void kernel_launch(void* const* d_in, const int* in_sizes, int n_in,
                              void* d_out, int out_size){
  const int*   x         = (const int*)  d_in[0];
  const float* enc_embed = (const float*)d_in[1];
  const float* enc_wx    = (const float*)d_in[2];
  const float* enc_wh    = (const float*)d_in[3];
  const float* enc_b     = (const float*)d_in[4];
  const float* dec_embed = (const float*)d_in[5];
  const float* attn_w    = (const float*)d_in[6];
  const float* attn_b    = (const float*)d_in[7];
  const float* comb_w    = (const float*)d_in[8];
  const float* comb_b    = (const float*)d_in[9];
  const float* dec_wx    = (const float*)d_in[10];
  const float* dec_wh    = (const float*)d_in[11];
  const float* dec_b     = (const float*)d_in[12];
  const float* out_w     = (const float*)d_in[13];
  const float* out_b     = (const float*)d_in[14];
  float* out = (float*)d_out;

  // device pointers to __device__ globals for k_T dst
  u32 *p_owT, *p_whT, *p_gwT, *p_cwT;
  cudaGetSymbolAddress((void**)&p_owT, d_owT);
  cudaGetSymbolAddress((void**)&p_whT, d_whT);
  cudaGetSymbolAddress((void**)&p_gwT, d_gwT);
  cudaGetSymbolAddress((void**)&p_cwT, d_cwT);

  k_init<<<128,256>>>();
  k_T<<<500*16,256>>>(out_w,   V,  p_owT, 512,  0,   500);  // out_w^T
  k_T<<<64*16, 256>>>(enc_wh,  G4, p_whT, 512,  0,   64);   // enc_wh^T
  k_T<<<64*16, 256>>>(dec_wx,  G4, p_gwT, 1024, 0,   64);   // dec_wx^T (K 0..1023)
  k_T<<<64*16, 256>>>(dec_wh,  G4, p_gwT, 1024, 512, 64);   // dec_wh^T (K 1024..2047)
  k_T<<<16*32, 256>>>(comb_w,  H,  p_cwT, 1024, 0,   16);   // comb_w^T
  k_xg<<<2048,256>>>(x, enc_embed, enc_wx, enc_b);
  for (int t=0;t<64;t++){
    k_mm_bf16<<<256,256>>>(0);       // h @ enc_wh -> gpart
    k_enc_point<<<128,256>>>(t);
  }
  k_init<<<128,256>>>();
  for (int t=0;t<64;t++){
    k_attn1<<<256,256>>>(dec_embed, attn_w);
    k_attn_ctx<<<128,256>>>(attn_b);
    k_mm_bf16<<<64,256>>>(2);        // concat(e,ctx) @ comb_w -> cpart
    k_combfin<<<128,256>>>(comb_b);
    k_mm_bf16<<<256,256>>>(1);       // concat(cin,h) @ [wx;wh] -> gpart
    k_dec_point<<<128,256>>>(dec_b);
    k_logits_mma<<<250,256>>>(out_b, out, t);
    k_lsm2<<<512,256>>>(out, t);
  }
}